// round 4
// baseline (speedup 1.0000x reference)
#include <cuda_runtime.h>
#include <math.h>

// Problem constants (fixed by the dataset)
#define NB 2
#define NN 50000
#define NF 64
#define NH 32
#define FH 96              // F + H
#define T2 (NB * NN)       // 100000 task rows
#define BNH (NB * NN * NH) // 3,200,000 elements per output tensor

// Scratch: static __device__ arrays (no runtime allocation allowed)
__device__ int    g_is64;          // 1 if edge_index is int64, 0 if int32
__device__ int    g_deg[NN];
__device__ float  g_dinv[NN];
__device__ float4 g_y[NN * 48];    // per node: 48 float4 = [b=0: 24][b=1: 24]
__device__ float4 g_agg[NN * 48];  // edge-aggregated features, same layout

// ---------------------------------------------------------------------------
// Index loader: branches on detected dtype (uniform branch, ~free)
__device__ __forceinline__ int load_idx(const void* ei, long long pos, int is64) {
    if (is64) return (int)((const long long*)ei)[pos];
    return ((const int*)ei)[pos];
}

// K_detect: decide int64 vs int32 from the first 256 values.
// True int64 indices are in [0, NN); int32 pairs read as int64 are >= 2^32
// unless the hi word is zero (prob ~2e-5 per sample -> ~0 over 256).
__global__ void k_detect(const void* ei) {
    int t = threadIdx.x;
    if (t == 0) g_is64 = 1;
    __syncthreads();
    long long v = ((const long long*)ei)[t];   // 256 int64 slots = 2KB, always in-bounds
    if (v < 0 || v >= NN) atomicAnd(&g_is64, 0);
}

// K0: zero the aggregation buffer, init deg = 1 (self-loop)
__global__ void k_init() {
    int i = blockIdx.x * blockDim.x + threadIdx.x;
    if (i < NN * 48) g_agg[i] = make_float4(0.f, 0.f, 0.f, 0.f);
    if (i < NN) g_deg[i] = 1;
}

// K1: in-degree count over edge targets
__global__ void k_deg(const void* __restrict__ ei, int E) {
    int e = blockIdx.x * blockDim.x + threadIdx.x;
    if (e >= E) return;
    int d = load_idx(ei, (long long)E + e, g_is64);
    if (d >= 0 && d < NN) atomicAdd(&g_deg[d], 1);
}

// K2: dinv = rsqrt(deg)
__global__ void k_dinv() {
    int n = blockIdx.x * blockDim.x + threadIdx.x;
    if (n < NN) g_dinv[n] = rsqrtf((float)g_deg[n]);
}

// K3: y[n][b][:] = dinv[n] * concat(x[b][n], h[b][n])
__global__ void k_scale(const float4* __restrict__ x4, const float4* __restrict__ h4) {
    int i = blockIdx.x * blockDim.x + threadIdx.x;  // over NN*48 float4s
    if (i >= NN * 48) return;
    int n  = i / 48;
    int r  = i % 48;
    int b  = r / 24;
    int k4 = r % 24;
    float4 v;
    if (k4 < 16) v = x4[(b * NN + n) * 16 + k4];
    else         v = h4[(b * NN + n) * 8 + (k4 - 16)];
    float s = g_dinv[n];
    v.x *= s; v.y *= s; v.z *= s; v.w *= s;
    g_y[i] = v;
}

// ---------------------------------------------------------------------------
// K4: edge gather/scatter — one warp per edge, 192 floats (both batches).
// Scalar atomicAdd, coalesced 128B per iteration.
__global__ void k_edge(const void* __restrict__ ei, int E) {
    int g    = blockIdx.x * blockDim.x + threadIdx.x;
    int e    = g >> 5;
    int lane = g & 31;
    if (e >= E) return;
    int is64 = g_is64;
    int s = load_idx(ei, e, is64);
    int d = load_idx(ei, (long long)E + e, is64);
    if ((unsigned)s >= NN || (unsigned)d >= NN) return;
    const float* ys = (const float*)(g_y)  + (long long)s * 192;
    float*       ad = (float*)(g_agg)      + (long long)d * 192;
#pragma unroll
    for (int t = 0; t < 6; t++) {
        int c = lane + 32 * t;
        atomicAdd(ad + c, ys[c]);
    }
}

// ---------------------------------------------------------------------------
// K5: fused  vec = dinv*(agg + y);  conv = vec@W + b;  LSTM gates; store h,c
__global__ void k_final(const float* __restrict__ W, const float* __restrict__ bias,
                        const float* __restrict__ c_cur, float* __restrict__ out,
                        int out_size) {
    extern __shared__ float smem[];
    float*  sW  = smem;                       // 96*128 = 12288 floats
    float*  sB  = sW + 12288;                 // 128 floats
    float4* sA4 = (float4*)(sB + 128);        // 64 rows * 24 float4

    int tid = threadIdx.x;
    int tx  = tid & 31;
    int ty  = tid >> 5;
    int row0 = blockIdx.x * 64;

    // load W (3072 float4) + bias
    const float4* W4 = (const float4*)W;
    float4* sW4 = (float4*)sW;
#pragma unroll
    for (int t = 0; t < 12; t++) sW4[tid + t * 256] = W4[tid + t * 256];
    if (tid < 32) ((float4*)sB)[tid] = ((const float4*)bias)[tid];

    // load A tile: vec = dinv * (agg + y); row grow=n*2+b lives at [grow*24+k4]
#pragma unroll
    for (int t = 0; t < 6; t++) {
        int f  = tid + t * 256;               // < 1536
        int r  = f / 24;
        int k4 = f % 24;
        int grow = row0 + r;
        float4 val = make_float4(0.f, 0.f, 0.f, 0.f);
        if (grow < T2) {
            float4 a = g_agg[grow * 24 + k4];
            float4 y = g_y[grow * 24 + k4];
            float  s = g_dinv[grow >> 1];
            val.x = s * (a.x + y.x);
            val.y = s * (a.y + y.y);
            val.z = s * (a.z + y.z);
            val.w = s * (a.w + y.w);
        }
        sA4[f] = val;
    }
    __syncthreads();

    float acc[8][4];
#pragma unroll
    for (int i = 0; i < 8; i++)
#pragma unroll
        for (int j = 0; j < 4; j++) acc[i][j] = 0.f;

    const float* Arow = (const float*)sA4 + (ty * 8) * 96;

#pragma unroll 4
    for (int k = 0; k < 96; k++) {
        float w0 = sW[k * 128 + tx];
        float w1 = sW[k * 128 + tx + 32];
        float w2 = sW[k * 128 + tx + 64];
        float w3 = sW[k * 128 + tx + 96];
#pragma unroll
        for (int i = 0; i < 8; i++) {
            float a = Arow[i * 96 + k];
            acc[i][0] += a * w0;
            acc[i][1] += a * w1;
            acc[i][2] += a * w2;
            acc[i][3] += a * w3;
        }
    }

    float bi = sB[tx], bf = sB[32 + tx], bo = sB[64 + tx], bg = sB[96 + tx];
    bool write_c = (out_size >= 2 * BNH);

#pragma unroll
    for (int i = 0; i < 8; i++) {
        int grow = row0 + ty * 8 + i;
        if (grow < T2) {
            int n = grow >> 1, b = grow & 1;
            float ig = 1.f / (1.f + expf(-(acc[i][0] + bi)));
            float fg = 1.f / (1.f + expf(-(acc[i][1] + bf)));
            float og = 1.f / (1.f + expf(-(acc[i][2] + bo)));
            float gg = tanhf(acc[i][3] + bg);
            int off = (b * NN + n) * NH + tx;
            float cn = fg * c_cur[off] + ig * gg;
            out[off] = og * tanhf(cn);         // h_next
            if (write_c) out[BNH + off] = cn;  // c_next
        }
    }
}

// ---------------------------------------------------------------------------
extern "C" void kernel_launch(void* const* d_in, const int* in_sizes, int n_in,
                              void* d_out, int out_size) {
    const float* x    = (const float*)d_in[0];
    const void*  ei   = d_in[1];
    const float* h    = (const float*)d_in[2];
    const float* c    = (const float*)d_in[3];
    const float* W    = (const float*)d_in[4];
    const float* bias = (const float*)d_in[5];
    float*       out  = (float*)d_out;
    int E = in_sizes[1] / 2;   // element count -> E for either dtype

    k_detect<<<1, 256>>>(ei);
    k_init<<<(NN * 48 + 255) / 256, 256>>>();
    k_deg<<<(E + 255) / 256, 256>>>(ei, E);
    k_dinv<<<(NN + 255) / 256, 256>>>();
    k_scale<<<(NN * 48 + 255) / 256, 256>>>((const float4*)x, (const float4*)h);
    {
        long long threads = (long long)E * 32;
        int blocks = (int)((threads + 255) / 256);
        k_edge<<<blocks, 256>>>(ei, E);
    }

    const int SMEM = (12288 + 128) * 4 + 64 * 24 * 16;  // 74240 B
    cudaFuncSetAttribute(k_final, cudaFuncAttributeMaxDynamicSharedMemorySize, SMEM);
    k_final<<<(T2 + 63) / 64, 256, SMEM>>>(W, bias, c, out, out_size);
}

// round 5
// speedup vs baseline: 1.2956x; 1.2956x over previous
#include <cuda_runtime.h>
#include <math.h>

// Problem constants (fixed by the dataset)
#define NB 2
#define NN 50000
#define NF 64
#define NH 32
#define FH 96              // F + H
#define T2 (NB * NN)       // 100000 task rows
#define BNH (NB * NN * NH) // 3,200,000 elements per output tensor

// Scratch: static __device__ arrays (no runtime allocation allowed)
__device__ int    g_is64;          // 1 if edge_index is int64, 0 if int32
__device__ int    g_deg[NN];
__device__ float  g_dinv[NN];
__device__ float4 g_y[NN * 48];    // per node: 48 float4 = [b=0: 24][b=1: 24]
__device__ float4 g_agg[NN * 48];  // edge-aggregated features, same layout

// ---------------------------------------------------------------------------
__device__ __forceinline__ int load_idx(const void* ei, long long pos, int is64) {
    if (is64) return (int)((const long long*)ei)[pos];
    return ((const int*)ei)[pos];
}

// K_detect: decide int64 vs int32 from the first 256 values.
// True int64 indices are in [0, NN); int32 pairs read as int64 are >= 2^32
// unless the hi word is zero (prob ~2e-5 per sample -> ~0 over 256).
__global__ void k_detect(const void* ei) {
    int t = threadIdx.x;
    if (t == 0) g_is64 = 1;
    __syncthreads();
    long long v = ((const long long*)ei)[t];
    if (v < 0 || v >= NN) atomicAnd(&g_is64, 0);
}

// K0: zero the aggregation buffer, init deg = 1 (self-loop)
__global__ void k_init() {
    int i = blockIdx.x * blockDim.x + threadIdx.x;
    if (i < NN * 48) g_agg[i] = make_float4(0.f, 0.f, 0.f, 0.f);
    if (i < NN) g_deg[i] = 1;
}

// K1: in-degree count over edge targets
__global__ void k_deg(const void* __restrict__ ei, int E) {
    int e = blockIdx.x * blockDim.x + threadIdx.x;
    if (e >= E) return;
    int d = load_idx(ei, (long long)E + e, g_is64);
    if ((unsigned)d < NN) atomicAdd(&g_deg[d], 1);
}

// K2: dinv = rsqrt(deg)
__global__ void k_dinv() {
    int n = blockIdx.x * blockDim.x + threadIdx.x;
    if (n < NN) g_dinv[n] = rsqrtf((float)g_deg[n]);
}

// K3: y[n][b][:] = dinv[n] * concat(x[b][n], h[b][n])
__global__ void k_scale(const float4* __restrict__ x4, const float4* __restrict__ h4) {
    int i = blockIdx.x * blockDim.x + threadIdx.x;  // over NN*48 float4s
    if (i >= NN * 48) return;
    int n  = i / 48;
    int r  = i % 48;
    int b  = r / 24;
    int k4 = r % 24;
    float4 v;
    if (k4 < 16) v = x4[(b * NN + n) * 16 + k4];
    else         v = h4[(b * NN + n) * 8 + (k4 - 16)];
    float s = g_dinv[n];
    v.x *= s; v.y *= s; v.z *= s; v.w *= s;
    g_y[i] = v;
}

// ---------------------------------------------------------------------------
// K4: edge gather/scatter — HALF-WARP per edge, 48 vec4 in 3 uniform steps.
// Vectorized reduction: red.global.add.v4.f32 on an explicitly-global address
// (addresses now proven valid; cvta pins the address space).
__device__ __forceinline__ void red4(float4* p, float4 v) {
    unsigned long long gp = (unsigned long long)__cvta_generic_to_global(p);
    asm volatile("red.global.add.v4.f32 [%0], {%1,%2,%3,%4};"
                 :: "l"(gp), "f"(v.x), "f"(v.y), "f"(v.z), "f"(v.w) : "memory");
}

__global__ void k_edge(const void* __restrict__ ei, int E) {
    int g    = blockIdx.x * blockDim.x + threadIdx.x;
    int e    = g >> 4;          // 16 lanes per edge
    int lane = g & 15;
    if (e >= E) return;
    int is64 = g_is64;
    int s = load_idx(ei, e, is64);
    int d = load_idx(ei, (long long)E + e, is64);
    if ((unsigned)s >= NN || (unsigned)d >= NN) return;
    const float4* ys = g_y   + (long long)s * 48;
    float4*       ad = g_agg + (long long)d * 48;
#pragma unroll
    for (int t = 0; t < 3; t++) {
        int c = lane + 16 * t;
        red4(ad + c, ys[c]);
    }
}

// ---------------------------------------------------------------------------
// K5: fused  vec = dinv*(agg + y);  conv = vec@W + b;  LSTM gates; store h,c
__global__ void k_final(const float* __restrict__ W, const float* __restrict__ bias,
                        const float* __restrict__ c_cur, float* __restrict__ out,
                        int out_size) {
    extern __shared__ float smem[];
    float*  sW  = smem;                       // 96*128 = 12288 floats
    float*  sB  = sW + 12288;                 // 128 floats
    float4* sA4 = (float4*)(sB + 128);        // 64 rows * 24 float4

    int tid = threadIdx.x;
    int tx  = tid & 31;
    int ty  = tid >> 5;
    int row0 = blockIdx.x * 64;

    // load W (3072 float4) + bias
    const float4* W4 = (const float4*)W;
    float4* sW4 = (float4*)sW;
#pragma unroll
    for (int t = 0; t < 12; t++) sW4[tid + t * 256] = W4[tid + t * 256];
    if (tid < 32) ((float4*)sB)[tid] = ((const float4*)bias)[tid];

    // load A tile: vec = dinv * (agg + y); row grow=n*2+b lives at [grow*24+k4]
#pragma unroll
    for (int t = 0; t < 6; t++) {
        int f  = tid + t * 256;               // < 1536
        int r  = f / 24;
        int k4 = f % 24;
        int grow = row0 + r;
        float4 val = make_float4(0.f, 0.f, 0.f, 0.f);
        if (grow < T2) {
            float4 a = g_agg[grow * 24 + k4];
            float4 y = g_y[grow * 24 + k4];
            float  s = g_dinv[grow >> 1];
            val.x = s * (a.x + y.x);
            val.y = s * (a.y + y.y);
            val.z = s * (a.z + y.z);
            val.w = s * (a.w + y.w);
        }
        sA4[f] = val;
    }
    __syncthreads();

    float acc[8][4];
#pragma unroll
    for (int i = 0; i < 8; i++)
#pragma unroll
        for (int j = 0; j < 4; j++) acc[i][j] = 0.f;

    const float* Arow = (const float*)sA4 + (ty * 8) * 96;

#pragma unroll 4
    for (int k = 0; k < 96; k++) {
        float w0 = sW[k * 128 + tx];
        float w1 = sW[k * 128 + tx + 32];
        float w2 = sW[k * 128 + tx + 64];
        float w3 = sW[k * 128 + tx + 96];
#pragma unroll
        for (int i = 0; i < 8; i++) {
            float a = Arow[i * 96 + k];
            acc[i][0] += a * w0;
            acc[i][1] += a * w1;
            acc[i][2] += a * w2;
            acc[i][3] += a * w3;
        }
    }

    float bi = sB[tx], bf = sB[32 + tx], bo = sB[64 + tx], bg = sB[96 + tx];
    bool write_c = (out_size >= 2 * BNH);

#pragma unroll
    for (int i = 0; i < 8; i++) {
        int grow = row0 + ty * 8 + i;
        if (grow < T2) {
            int n = grow >> 1, b = grow & 1;
            float ig = 1.f / (1.f + expf(-(acc[i][0] + bi)));
            float fg = 1.f / (1.f + expf(-(acc[i][1] + bf)));
            float og = 1.f / (1.f + expf(-(acc[i][2] + bo)));
            float gg = tanhf(acc[i][3] + bg);
            int off = (b * NN + n) * NH + tx;
            float cn = fg * c_cur[off] + ig * gg;
            out[off] = og * tanhf(cn);         // h_next
            if (write_c) out[BNH + off] = cn;  // c_next
        }
    }
}

// ---------------------------------------------------------------------------
extern "C" void kernel_launch(void* const* d_in, const int* in_sizes, int n_in,
                              void* d_out, int out_size) {
    const float* x    = (const float*)d_in[0];
    const void*  ei   = d_in[1];
    const float* h    = (const float*)d_in[2];
    const float* c    = (const float*)d_in[3];
    const float* W    = (const float*)d_in[4];
    const float* bias = (const float*)d_in[5];
    float*       out  = (float*)d_out;
    int E = in_sizes[1] / 2;   // element count -> E for either dtype

    k_detect<<<1, 256>>>(ei);
    k_init<<<(NN * 48 + 255) / 256, 256>>>();
    k_deg<<<(E + 255) / 256, 256>>>(ei, E);
    k_dinv<<<(NN + 255) / 256, 256>>>();
    k_scale<<<(NN * 48 + 255) / 256, 256>>>((const float4*)x, (const float4*)h);
    {
        long long threads = (long long)E * 16;
        int blocks = (int)((threads + 255) / 256);
        k_edge<<<blocks, 256>>>(ei, E);
    }

    const int SMEM = (12288 + 128) * 4 + 64 * 24 * 16;  // 74240 B
    cudaFuncSetAttribute(k_final, cudaFuncAttributeMaxDynamicSharedMemorySize, SMEM);
    k_final<<<(T2 + 63) / 64, 256, SMEM>>>(W, bias, c, out, out_size);
}